// round 15
// baseline (speedup 1.0000x reference)
#include <cuda_runtime.h>
#include <cuda_fp16.h>
#include <math.h>
#include <stdint.h>

// ---------------------------------------------------------------------------
// QuantumKernelMethod: 4 qubits, 2 layers.  FULLY FUSED single kernel.
// z(i,j) = | u_i^H M_j u_i |, u_i = A(a_i)|0>, M_j = A(b_j) Z0 A(b_j)^H.
// A(x) = U_fixed * (tensor_q Ry(x_q));  M = I - 2 B B^H, B = A[:,8:16].
// Gram = | F[1024x256] * G^T |.  Each 128x64 GEMM block computes its own
// F/G feature tiles in shared memory (statevector sim + Hermitian features),
// then runs the fp16 m16n8k16 MMA mainloop on them. No global F/G arrays.
// ---------------------------------------------------------------------------

#define NROWS 1024
#define FDIM 256
#define ROW_BYTES 512

#define BM 128
#define BN 64

// dynamic smem layout (bytes from base)
#define AS_OFF   0                       // [128][256] halves, 64KB (aliased by stG)
#define BS_OFF   65536                   // [64][256] halves, 32KB
#define STF_OFF  98304                   // [128][16] float2, 16KB
#define SHS_OFF  114688                  // [16][17] float2, 2176B
#define SHU_OFF  116864                  // [8][4] float2, 256B
#define SC_OFF   117120                  // [192][8] float, 6144B (sincos per row)
#define PQ_OFF   123264                  // [120] int, 480B
#define FUSED_SMEM 123776

// swizzled half-index within a 256-half row: 16B chunk ^= (row & 7)
__device__ __forceinline__ int sw_h(int row, int t) {
    return ((((t >> 3) ^ (row & 7)) << 3) | (t & 7));
}

// CNOT ring (0,1)(1,2)(2,3)(3,0) as a basis-index permutation
__device__ __forceinline__ int cnot_perm(int idx) {
    if (idx & 8) idx ^= 4;
    if (idx & 4) idx ^= 2;
    if (idx & 2) idx ^= 1;
    if (idx & 1) idx ^= 8;
    return idx;
}

// idx in [0,120) -> (p,q), p<q<16 (used ONCE per block to fill the pq table)
__device__ __forceinline__ void pq_from_idx(int idx, int& p, int& q) {
    float d = 240.25f - 2.f * (float)idx;
    p = (int)(15.5f - sqrtf(d));
    if (p < 0) p = 0;
    int rem = idx - (15 * p - ((p * (p - 1)) >> 1));
    while (rem < 0) { p--; rem = idx - (15 * p - ((p * (p - 1)) >> 1)); }
    while (rem >= 15 - p) { rem -= 15 - p; p++; }
    q = p + 1 + rem;
}

__global__ __launch_bounds__(512) void fused_qkm(const float* __restrict__ a,
                                                 const float* __restrict__ b,
                                                 const float* __restrict__ params,
                                                 float* __restrict__ C) {
    extern __shared__ __align__(16) char smem[];
    __half*  As   = (__half*)(smem + AS_OFF);          // final F tile (swizzled)
    __half*  Bs   = (__half*)(smem + BS_OFF);          // final G tile (swizzled)
    float2*  stG  = (float2*)(smem + AS_OFF);          // [64][16][8] aliases As
    float2*  stF  = (float2*)(smem + STF_OFF);         // [128][16]
    float2 (*shS)[17] = (float2(*)[17])(smem + SHS_OFF);
    float2 (*shU)[4]  = (float2(*)[4])(smem + SHU_OFF);
    float*   sc   = (float*)(smem + SC_OFF);           // [192][8]: cq[4],sq[4]
    int*     pqt  = (int*)(smem + PQ_OFF);             // [120]: p | q<<8

    int tid = threadIdx.x;
    int i0 = blockIdx.y * BM;   // F rows [i0, i0+128)
    int j0 = blockIdx.x * BN;   // G rows [j0, j0+64)

    // ---- phase 1: params mats + pq table + per-row sincos --------------------
    if (tid < 8) {
        float pa = params[tid * 3 + 0], pb = params[tid * 3 + 1], pc = params[tid * 3 + 2];
        float sa, ca, sb, cb, s_c, cc;
        __sincosf(0.5f * pa, &sa, &ca);
        __sincosf(0.5f * pb, &sb, &cb);
        __sincosf(0.5f * pc, &s_c, &cc);
        float2 m00 = make_float2(cb * ca,  sb * sa);
        float2 m01 = make_float2(-sb * ca, -cb * sa);
        float2 m10 = make_float2(sb * ca, -cb * sa);
        float2 m11 = make_float2(cb * ca, -sb * sa);
        shU[tid][0] = make_float2(cc * m00.x + s_c * m00.y, cc * m00.y - s_c * m00.x);
        shU[tid][1] = make_float2(cc * m01.x + s_c * m01.y, cc * m01.y - s_c * m01.x);
        shU[tid][2] = make_float2(cc * m10.x - s_c * m10.y, cc * m10.y + s_c * m10.x);
        shU[tid][3] = make_float2(cc * m11.x - s_c * m11.y, cc * m11.y + s_c * m11.x);
    }
    if (tid < 120) {
        int p, q; pq_from_idx(tid, p, q);
        pqt[tid] = p | (q << 8);
    }
    if (tid < 64) {            // G rows
        float4 xv = *(const float4*)&b[(j0 + tid) * 4];
        float* s = &sc[tid * 8];
        __sincosf(0.5f * xv.x, &s[4], &s[0]);
        __sincosf(0.5f * xv.y, &s[5], &s[1]);
        __sincosf(0.5f * xv.z, &s[6], &s[2]);
        __sincosf(0.5f * xv.w, &s[7], &s[3]);
    } else if (tid < 192) {    // F rows
        int r = tid - 64;
        float4 xv = *(const float4*)&a[(i0 + r) * 4];
        float* s = &sc[(64 + r) * 8];
        __sincosf(0.5f * xv.x, &s[4], &s[0]);
        __sincosf(0.5f * xv.y, &s[5], &s[1]);
        __sincosf(0.5f * xv.z, &s[6], &s[2]);
        __sincosf(0.5f * xv.w, &s[7], &s[3]);
    }
    // U_fixed init (tid<128: 16 cols x 8 pairs)
    {
        bool act = tid < 128;
        int ucol = tid & 15, pr = (tid >> 4) & 7;
        if (act) {
#pragma unroll
            for (int h = 0; h < 2; h++) {
                int amp = pr * 2 + h;
                shS[ucol][amp] = make_float2((amp == ucol) ? 1.f : 0.f, 0.f);
            }
        }
        __syncthreads();

#pragma unroll
        for (int l = 0; l < 2; l++) {
#pragma unroll
            for (int i = 0; i < 4; i++) {
                int m = 8 >> i;
                int lo = pr & (m - 1);
                int idx0 = ((pr & ~(m - 1)) << 1) | lo;
                int idx1 = idx0 | m;
                float2 n0, n1;
                if (act) {
                    float2 x0 = shS[ucol][idx0];
                    float2 x1 = shS[ucol][idx1];
                    float2 U00 = shU[l * 4 + i][0], U01 = shU[l * 4 + i][1];
                    float2 U10 = shU[l * 4 + i][2], U11 = shU[l * 4 + i][3];
                    n0.x = U00.x * x0.x - U00.y * x0.y + U01.x * x1.x - U01.y * x1.y;
                    n0.y = U00.x * x0.y + U00.y * x0.x + U01.x * x1.y + U01.y * x1.x;
                    n1.x = U10.x * x0.x - U10.y * x0.y + U11.x * x1.x - U11.y * x1.y;
                    n1.y = U10.x * x0.y + U10.y * x0.x + U11.x * x1.y + U11.y * x1.x;
                }
                if (i == 3) {
                    __syncthreads();
                    if (act) {
                        shS[ucol][cnot_perm(idx0)] = n0;
                        shS[ucol][cnot_perm(idx1)] = n1;
                    }
                } else if (act) {
                    shS[ucol][idx0] = n0;
                    shS[ucol][idx1] = n1;
                }
                __syncthreads();
            }
        }
    }
    // shS[k][p] = U_fixed[p][k]

    // ---- phase 2: G statevectors (64 rows x 8 cols; stG aliases As) ----------
    {
        int r = tid >> 3, c = tid & 7;
        const float* s = &sc[r * 8];
        float f0[4], f1[4];
        f0[0] = -s[4]; f1[0] = s[0];
#pragma unroll
        for (int q = 1; q < 4; q++) {
            int mq = (c >> (3 - q)) & 1;
            f0[q] = mq ? -s[4 + q] : s[q];
            f1[q] = mq ?  s[q] : s[4 + q];
        }
        float w[16];
#pragma unroll
        for (int k = 0; k < 16; k++) {
            float t0 = (k & 8) ? f1[0] : f0[0];
            float t1 = (k & 4) ? f1[1] : f0[1];
            float t2 = (k & 2) ? f1[2] : f0[2];
            float t3 = (k & 1) ? f1[3] : f0[3];
            w[k] = (t0 * t1) * (t2 * t3);
        }
#pragma unroll
        for (int p = 0; p < 16; p++) {
            float ux = 0.f, uy = 0.f;
#pragma unroll
            for (int k = 0; k < 16; k++) {
                float2 Upk = shS[k][p];
                ux += Upk.x * w[k];
                uy += Upk.y * w[k];
            }
            stG[(r * 16 + p) * 8 + c] = make_float2(ux, uy);
        }
    }
    __syncthreads();

    // ---- phase 3: G features -> Bs (swizzled halves) --------------------------
    {
        int r = tid >> 3, lane = tid & 7;
        __half* brow = Bs + r * FDIM;
#pragma unroll
        for (int h = 0; h < 2; h++) {
            int p = lane + 8 * h;
            float s2 = 0.f;
#pragma unroll
            for (int k = 0; k < 8; k++) {
                float2 v = stG[(r * 16 + p) * 8 + k];
                s2 += v.x * v.x + v.y * v.y;
            }
            brow[sw_h(r, p)] = __float2half_rn(1.f - 2.f * s2);
        }
#pragma unroll
        for (int it = 0; it < 15; it++) {
            int idx = lane + 8 * it;
            int pk = pqt[idx];
            int p = pk & 255, q = pk >> 8;
            float re = 0.f, im = 0.f;
#pragma unroll
            for (int k = 0; k < 8; k++) {
                float2 ap = stG[(r * 16 + p) * 8 + k];
                float2 aq = stG[(r * 16 + q) * 8 + k];
                re += ap.x * aq.x + ap.y * aq.y;
                im += ap.y * aq.x - ap.x * aq.y;
            }
            brow[sw_h(r, 16 + idx)]  = __float2half_rn(-2.f * re);
            brow[sw_h(r, 136 + idx)] = __float2half_rn(-2.f * im);
        }
    }
    __syncthreads();   // stG dead; As region free

    // ---- phase 4: F statevectors (128 rows x 4 lanes) -------------------------
    {
        int r = tid >> 2, lane = tid & 3;
        const float* s = &sc[(64 + r) * 8];
        float v[16];
#pragma unroll
        for (int k = 0; k < 16; k++) {
            float t0 = (k & 8) ? s[4] : s[0];
            float t1 = (k & 4) ? s[5] : s[1];
            float t2 = (k & 2) ? s[6] : s[2];
            float t3 = (k & 1) ? s[7] : s[3];
            v[k] = (t0 * t1) * (t2 * t3);
        }
#pragma unroll
        for (int h = 0; h < 4; h++) {
            int p = lane + 4 * h;
            float ux = 0.f, uy = 0.f;
#pragma unroll
            for (int k = 0; k < 16; k++) {
                float2 Upk = shS[k][p];
                ux += Upk.x * v[k];
                uy += Upk.y * v[k];
            }
            stF[r * 16 + p] = make_float2(ux, uy);
        }
    }
    __syncthreads();

    // ---- phase 5: F features -> As (swizzled halves) --------------------------
    {
        int r = tid >> 2, lane = tid & 3;
        __half* arow = As + r * FDIM;
        const float2* ur = &stF[r * 16];
#pragma unroll
        for (int h = 0; h < 4; h++) {
            int p = lane + 4 * h;
            float2 u = ur[p];
            arow[sw_h(r, p)] = __float2half_rn(u.x * u.x + u.y * u.y);
        }
#pragma unroll
        for (int it = 0; it < 30; it++) {
            int idx = lane + 4 * it;
            int pk = pqt[idx];
            int p = pk & 255, q = pk >> 8;
            float2 up = ur[p], uq = ur[q];
            arow[sw_h(r, 16 + idx)]  = __float2half_rn(2.f * (up.x * uq.x + up.y * uq.y));
            arow[sw_h(r, 136 + idx)] = __float2half_rn(2.f * (up.y * uq.x - up.x * uq.y));
        }
    }
    __syncthreads();

    // ---- phase 6: fp16 MMA mainloop (verified R14 structure) ------------------
    int warp = tid >> 5, lane = tid & 31;
    int wm = warp >> 2;          // 0..3
    int wn = warp & 3;           // 0..3
    int grp = lane >> 2;         // 0..7
    int tig = lane & 3;          // 0..3

    uint32_t as_addr = (uint32_t)__cvta_generic_to_shared(As);
    uint32_t bs_addr = (uint32_t)__cvta_generic_to_shared(Bs);

    int a_r = (lane & 7) + ((lane >> 3) & 1) * 8;
    int a_ck = (lane >> 4) & 1;
    int b_r = (lane & 7) + ((lane >> 4) & 1) * 8;
    int b_ck = (lane >> 3) & 1;

    uint32_t a_rowaddr[2]; int a_rm[2];
#pragma unroll
    for (int mt = 0; mt < 2; mt++) {
        int row = wm * 32 + mt * 16 + a_r;
        a_rowaddr[mt] = as_addr + row * ROW_BYTES;
        a_rm[mt] = row & 7;
    }
    int b_row = wn * 16 + b_r;
    uint32_t b_rowaddr = bs_addr + b_row * ROW_BYTES;
    int b_rm = b_row & 7;

    float acc[2][2][4];
#pragma unroll
    for (int mt = 0; mt < 2; mt++)
#pragma unroll
        for (int nt = 0; nt < 2; nt++)
#pragma unroll
            for (int r = 0; r < 4; r++) acc[mt][nt][r] = 0.f;

#pragma unroll
    for (int k16 = 0; k16 < 16; k16++) {
        uint32_t afr[2][4], bfr[2][2];
#pragma unroll
        for (int mt = 0; mt < 2; mt++) {
            uint32_t addr = a_rowaddr[mt] +
                (uint32_t)((((2 * k16 + a_ck) ^ a_rm[mt]) << 4));
            asm("ldmatrix.sync.aligned.m8n8.x4.shared.b16 {%0,%1,%2,%3}, [%4];"
                : "=r"(afr[mt][0]), "=r"(afr[mt][1]),
                  "=r"(afr[mt][2]), "=r"(afr[mt][3])
                : "r"(addr) : "memory");
        }
        {
            uint32_t addr = b_rowaddr +
                (uint32_t)((((2 * k16 + b_ck) ^ b_rm) << 4));
            asm("ldmatrix.sync.aligned.m8n8.x4.shared.b16 {%0,%1,%2,%3}, [%4];"
                : "=r"(bfr[0][0]), "=r"(bfr[0][1]),
                  "=r"(bfr[1][0]), "=r"(bfr[1][1])
                : "r"(addr) : "memory");
        }
#pragma unroll
        for (int mt = 0; mt < 2; mt++)
#pragma unroll
            for (int nt = 0; nt < 2; nt++) {
                asm("mma.sync.aligned.m16n8k16.row.col.f32.f16.f16.f32 "
                    "{%0,%1,%2,%3}, {%4,%5,%6,%7}, {%8,%9}, {%0,%1,%2,%3};"
                    : "+f"(acc[mt][nt][0]), "+f"(acc[mt][nt][1]),
                      "+f"(acc[mt][nt][2]), "+f"(acc[mt][nt][3])
                    : "r"(afr[mt][0]), "r"(afr[mt][1]),
                      "r"(afr[mt][2]), "r"(afr[mt][3]),
                      "r"(bfr[nt][0]), "r"(bfr[nt][1]));
            }
    }

    // ---- epilogue ----
#pragma unroll
    for (int mt = 0; mt < 2; mt++) {
        int rowg = i0 + wm * 32 + mt * 16 + grp;
#pragma unroll
        for (int nt = 0; nt < 2; nt++) {
            int colg = j0 + wn * 16 + nt * 8 + 2 * tig;
            float2 o0 = make_float2(fabsf(acc[mt][nt][0]), fabsf(acc[mt][nt][1]));
            float2 o1 = make_float2(fabsf(acc[mt][nt][2]), fabsf(acc[mt][nt][3]));
            *(float2*)&C[(size_t)rowg * NROWS + colg] = o0;
            *(float2*)&C[(size_t)(rowg + 8) * NROWS + colg] = o1;
        }
    }
}

// ---------------------------------------------------------------------------
extern "C" void kernel_launch(void* const* d_in, const int* in_sizes, int n_in,
                              void* d_out, int out_size) {
    const float* a = (const float*)d_in[0];       // [1024,4]
    const float* b = (const float*)d_in[1];       // [1024,4]
    const float* params = (const float*)d_in[2];  // [2,4,3]
    float* out = (float*)d_out;                   // [1024,1024]

    cudaFuncSetAttribute(fused_qkm,
                         cudaFuncAttributeMaxDynamicSharedMemorySize, FUSED_SMEM);

    dim3 grid(NROWS / BN, NROWS / BM);   // (16, 8) = 128 blocks, single wave
    fused_qkm<<<grid, 512, FUSED_SMEM>>>(a, b, params, out);
}

// round 16
// speedup vs baseline: 2.2525x; 2.2525x over previous
#include <cuda_runtime.h>
#include <cuda_fp16.h>
#include <math.h>
#include <stdint.h>

// ---------------------------------------------------------------------------
// QuantumKernelMethod: 4 qubits, 2 layers.
// z(i,j) = | u_i^H M_j u_i |, u_i = A(a_i)|0>, M_j = A(b_j) Z0 A(b_j)^H.
// A(x) = U_fixed * (tensor_q Ry(x_q)); U_fixed computed in-block (parallel).
// M = I - 2 B B^H, B = A[:,8:16].
// Gram = | F[1024x256] * G^T |, fp16 MMA (fp32 acc).
// R16: build uses a per-block pq lookup table; GEMM splits the A bulk copy
// into 4 row-quarters with per-quarter mbarriers so warps start as soon as
// their slice lands (B + 16KB instead of 96KB).
// ---------------------------------------------------------------------------

#define NROWS 1024
#define FDIM 256
#define ROW_HALVES 256
#define ROW_BYTES  512

__device__ __align__(16) __half g_F[NROWS * FDIM];
__device__ __align__(16) __half g_G[NROWS * FDIM];

// swizzled half2-index within a row: chunk(16B) index ^= (row & 7)
__device__ __forceinline__ int sw_t2(int row, int t2) {
    return ((((t2 >> 2) ^ (row & 7)) << 2) | (t2 & 3));
}

__device__ __forceinline__ void build_fused_mats(const float* params,
                                                 float2 (*shU)[4], int tid) {
    if (tid < 8) {
        float a = params[tid * 3 + 0], b = params[tid * 3 + 1], c = params[tid * 3 + 2];
        float sa, ca, sb, cb, sc, cc;
        __sincosf(0.5f * a, &sa, &ca);
        __sincosf(0.5f * b, &sb, &cb);
        __sincosf(0.5f * c, &sc, &cc);
        float2 m00 = make_float2(cb * ca,  sb * sa);
        float2 m01 = make_float2(-sb * ca, -cb * sa);
        float2 m10 = make_float2(sb * ca, -cb * sa);
        float2 m11 = make_float2(cb * ca, -sb * sa);
        shU[tid][0] = make_float2(cc * m00.x + sc * m00.y, cc * m00.y - sc * m00.x);
        shU[tid][1] = make_float2(cc * m01.x + sc * m01.y, cc * m01.y - sc * m01.x);
        shU[tid][2] = make_float2(cc * m10.x - sc * m10.y, cc * m10.y + sc * m10.x);
        shU[tid][3] = make_float2(cc * m11.x - sc * m11.y, cc * m11.y + sc * m11.x);
    }
}

__device__ __forceinline__ int cnot_perm(int idx) {
    if (idx & 8) idx ^= 4;
    if (idx & 4) idx ^= 2;
    if (idx & 2) idx ^= 1;
    if (idx & 1) idx ^= 8;
    return idx;
}

// idx in [0,120) -> (p,q); used once per block to fill the table
__device__ __forceinline__ void pq_from_idx(int idx, int& p, int& q) {
    float d = 240.25f - 2.f * (float)idx;
    p = (int)(15.5f - sqrtf(d));
    if (p < 0) p = 0;
    int rem = idx - (15 * p - ((p * (p - 1)) >> 1));
    while (rem < 0) { p--; rem = idx - (15 * p - ((p * (p - 1)) >> 1)); }
    while (rem >= 15 - p) { rem -= 15 - p; p++; }
    q = p + 1 + rem;
}

// ---- build kernel: 192 blocks x 128 threads ---------------------------------
#define F_BLOCKS 64
#define G_BLOCKS 128

__global__ __launch_bounds__(128) void build_features(const float* __restrict__ a,
                                                      const float* __restrict__ b,
                                                      const float* __restrict__ params) {
    __shared__ float2 shU[8][4];
    __shared__ float2 shS[16][17];
    __shared__ float2 sh_stF[16][16];
    __shared__ float2 sh_stG[8][16][9];
    __shared__ float  sh_f[16][256];
    __shared__ int    pqt[120];

    int tid = threadIdx.x;
    build_fused_mats(params, shU, tid);
    if (tid < 120) {
        int p, q; pq_from_idx(tid, p, q);
        pqt[tid] = p | (q << 8);
    }

    // ---- in-block parallel U_fixed: 16 columns x 8 pairs ----
    {
        int ucol = tid & 15, pr = tid >> 4;
#pragma unroll
        for (int h = 0; h < 2; h++) {
            int amp = pr * 2 + h;
            shS[ucol][amp] = make_float2((amp == ucol) ? 1.f : 0.f, 0.f);
        }
        __syncthreads();

#pragma unroll
        for (int l = 0; l < 2; l++) {
#pragma unroll
            for (int i = 0; i < 4; i++) {
                int m = 8 >> i;
                int lo = pr & (m - 1);
                int idx0 = ((pr & ~(m - 1)) << 1) | lo;
                int idx1 = idx0 | m;

                float2 x0 = shS[ucol][idx0];
                float2 x1 = shS[ucol][idx1];
                float2 U00 = shU[l * 4 + i][0], U01 = shU[l * 4 + i][1];
                float2 U10 = shU[l * 4 + i][2], U11 = shU[l * 4 + i][3];
                float2 n0, n1;
                n0.x = U00.x * x0.x - U00.y * x0.y + U01.x * x1.x - U01.y * x1.y;
                n0.y = U00.x * x0.y + U00.y * x0.x + U01.x * x1.y + U01.y * x1.x;
                n1.x = U10.x * x0.x - U10.y * x0.y + U11.x * x1.x - U11.y * x1.y;
                n1.y = U10.x * x0.y + U10.y * x0.x + U11.x * x1.y + U11.y * x1.x;

                if (i == 3) {
                    __syncthreads();
                    shS[ucol][cnot_perm(idx0)] = n0;
                    shS[ucol][cnot_perm(idx1)] = n1;
                } else {
                    shS[ucol][idx0] = n0;
                    shS[ucol][idx1] = n1;
                }
                __syncthreads();
            }
        }
    }

    bool isF = blockIdx.x < F_BLOCKS;

    if (isF) {
        int g = tid >> 3, l = tid & 7;
        int row = blockIdx.x * 16 + g;
        float4 xv = *(const float4*)&a[row * 4];
        float cq[4], sq[4];
        __sincosf(0.5f * xv.x, &sq[0], &cq[0]);
        __sincosf(0.5f * xv.y, &sq[1], &cq[1]);
        __sincosf(0.5f * xv.z, &sq[2], &cq[2]);
        __sincosf(0.5f * xv.w, &sq[3], &cq[3]);

        float v[16];
#pragma unroll
        for (int k = 0; k < 16; k++) {
            float t0 = (k & 8) ? sq[0] : cq[0];
            float t1 = (k & 4) ? sq[1] : cq[1];
            float t2 = (k & 2) ? sq[2] : cq[2];
            float t3 = (k & 1) ? sq[3] : cq[3];
            v[k] = (t0 * t1) * (t2 * t3);
        }
#pragma unroll
        for (int h = 0; h < 2; h++) {
            int p = l + 8 * h;
            float ux = 0.f, uy = 0.f;
#pragma unroll
            for (int k = 0; k < 16; k++) {
                float2 Upk = shS[k][p];
                ux += Upk.x * v[k];
                uy += Upk.y * v[k];
            }
            sh_stF[g][p] = make_float2(ux, uy);
        }
        __syncthreads();

#pragma unroll
        for (int h = 0; h < 2; h++) {
            int p = l + 8 * h;
            float2 u = sh_stF[g][p];
            sh_f[g][p] = u.x * u.x + u.y * u.y;
        }
#pragma unroll
        for (int it = 0; it < 15; it++) {
            int idx = l + 8 * it;
            int pk = pqt[idx];
            int p = pk & 255, q = pk >> 8;
            float2 up = sh_stF[g][p], uq = sh_stF[g][q];
            sh_f[g][16 + idx]  = 2.f * (up.x * uq.x + up.y * uq.y);
            sh_f[g][136 + idx] = 2.f * (up.y * uq.x - up.x * uq.y);
        }
        __syncthreads();

        __half2* dst = (__half2*)g_F;
        int r0 = blockIdx.x * 16;
#pragma unroll
        for (int it = 0; it < 16; it++) {
            int flat = it * 128 + tid;
            int rl = flat >> 7, t2 = flat & 127;
            __half2 o = __floats2half2_rn(sh_f[rl][2 * t2], sh_f[rl][2 * t2 + 1]);
            int row_g = r0 + rl;
            dst[(size_t)row_g * (ROW_HALVES / 2) + sw_t2(row_g, t2)] = o;
        }
    } else {
        int g = tid >> 4, l = tid & 15;
        int col = l & 7, half = l >> 3;
        int row = (blockIdx.x - F_BLOCKS) * 8 + g;
        float4 xv = *(const float4*)&b[row * 4];
        float cq[4], sq[4];
        __sincosf(0.5f * xv.x, &sq[0], &cq[0]);
        __sincosf(0.5f * xv.y, &sq[1], &cq[1]);
        __sincosf(0.5f * xv.z, &sq[2], &cq[2]);
        __sincosf(0.5f * xv.w, &sq[3], &cq[3]);

        float f0[4], f1[4];
        f0[0] = -sq[0]; f1[0] = cq[0];
#pragma unroll
        for (int q = 1; q < 4; q++) {
            int mq = (col >> (3 - q)) & 1;
            f0[q] = mq ? -sq[q] : cq[q];
            f1[q] = mq ?  cq[q] : sq[q];
        }
        float w[16];
#pragma unroll
        for (int k = 0; k < 16; k++) {
            float t0 = (k & 8) ? f1[0] : f0[0];
            float t1 = (k & 4) ? f1[1] : f0[1];
            float t2 = (k & 2) ? f1[2] : f0[2];
            float t3 = (k & 1) ? f1[3] : f0[3];
            w[k] = (t0 * t1) * (t2 * t3);
        }
#pragma unroll
        for (int pi = 0; pi < 8; pi++) {
            int p = half * 8 + pi;
            float ux = 0.f, uy = 0.f;
#pragma unroll
            for (int k = 0; k < 16; k++) {
                float2 Upk = shS[k][p];
                ux += Upk.x * w[k];
                uy += Upk.y * w[k];
            }
            sh_stG[g][p][col] = make_float2(ux, uy);
        }
        __syncthreads();

        {
            float s2 = 0.f;
#pragma unroll
            for (int k = 0; k < 8; k++) {
                float2 v2 = sh_stG[g][l][k];
                s2 += v2.x * v2.x + v2.y * v2.y;
            }
            sh_f[g][l] = 1.f - 2.f * s2;
        }
#pragma unroll
        for (int it = 0; it < 8; it++) {
            int idx = l + 16 * it;
            if (idx >= 120) break;
            int pk = pqt[idx];
            int p = pk & 255, q = pk >> 8;
            float re = 0.f, im = 0.f;
#pragma unroll
            for (int k = 0; k < 8; k++) {
                float2 ap = sh_stG[g][p][k];
                float2 aq = sh_stG[g][q][k];
                re += ap.x * aq.x + ap.y * aq.y;
                im += ap.y * aq.x - ap.x * aq.y;
            }
            sh_f[g][16 + idx]  = -2.f * re;
            sh_f[g][136 + idx] = -2.f * im;
        }
        __syncthreads();

        __half2* dst = (__half2*)g_G;
        int r0 = (blockIdx.x - F_BLOCKS) * 8;
#pragma unroll
        for (int it = 0; it < 8; it++) {
            int flat = it * 128 + tid;
            int rl = flat >> 7, t2 = flat & 127;
            __half2 o = __floats2half2_rn(sh_f[rl][2 * t2], sh_f[rl][2 * t2 + 1]);
            int row_g = r0 + rl;
            dst[(size_t)row_g * (ROW_HALVES / 2) + sw_t2(row_g, t2)] = o;
        }
    }
}

// ---- fp16 NT GEMM: 128x64 tile, 512 threads, quartered bulk-copy loads ------
// 16 warps (4m x 4n), warp tile 32x16, m16n8k16, fp32 acc.
// B: 1 bulk copy (32KB, own mbarrier). A: 4 bulk copies of 32-row quarters
// (16KB each, own mbarriers). Warp group wm waits on B + quarter wm only.

#define BM 128
#define BN 64
#define A_BYTES (BM * ROW_BYTES)          // 65536
#define B_BYTES (BN * ROW_BYTES)          // 32768
#define AQ_BYTES (A_BYTES / 4)            // 16384
#define GEMM_SMEM (A_BYTES + B_BYTES + 64)

__device__ __forceinline__ void mbar_wait(uint32_t addr) {
    uint32_t done = 0;
    while (!done) {
        asm volatile(
            "{\n\t.reg .pred p;\n\t"
            "mbarrier.try_wait.parity.acquire.cta.shared::cta.b64 p, [%1], 0;\n\t"
            "selp.b32 %0, 1, 0, p;\n\t}"
            : "=r"(done) : "r"(addr) : "memory");
    }
}

__global__ __launch_bounds__(512) void gemm_f16_abs(float* __restrict__ C) {
    extern __shared__ __align__(16) __half smem[];
    __half* As = smem;                        // [BM][256] swizzled rows
    __half* Bs = smem + BM * ROW_HALVES;      // [BN][256]
    uint64_t* mbar = (uint64_t*)(smem + (BM + BN) * ROW_HALVES);  // [5]

    int tid = threadIdx.x;
    int warp = tid >> 5, lane = tid & 31;
    int wm = warp >> 2;          // 0..3 -> A quarter
    int wn = warp & 3;           // 0..3
    int grp = lane >> 2;         // 0..7
    int tig = lane & 3;          // 0..3

    int i0 = blockIdx.y * BM;
    int j0 = blockIdx.x * BN;

    uint32_t mb_base = (uint32_t)__cvta_generic_to_shared(mbar);
    uint32_t as_addr = (uint32_t)__cvta_generic_to_shared(As);
    uint32_t bs_addr = (uint32_t)__cvta_generic_to_shared(Bs);

    if (tid == 0) {
#pragma unroll
        for (int s = 0; s < 5; s++)
            asm volatile("mbarrier.init.shared.b64 [%0], 1;"
                         :: "r"(mb_base + s * 8) : "memory");
    }
    __syncthreads();

    if (tid == 0) {
        // B first (everyone needs it)
        asm volatile("mbarrier.arrive.expect_tx.shared.b64 _, [%0], %1;"
                     :: "r"(mb_base + 4 * 8), "r"((uint32_t)B_BYTES) : "memory");
        asm volatile(
            "cp.async.bulk.shared::cta.global.mbarrier::complete_tx::bytes "
            "[%0], [%1], %2, [%3];"
            :: "r"(bs_addr), "l"(&g_G[(size_t)j0 * ROW_HALVES]),
               "r"((uint32_t)B_BYTES), "r"(mb_base + 4 * 8) : "memory");
        // A quarters in warp-group order
#pragma unroll
        for (int qd = 0; qd < 4; qd++) {
            asm volatile("mbarrier.arrive.expect_tx.shared.b64 _, [%0], %1;"
                         :: "r"(mb_base + qd * 8), "r"((uint32_t)AQ_BYTES) : "memory");
            asm volatile(
                "cp.async.bulk.shared::cta.global.mbarrier::complete_tx::bytes "
                "[%0], [%1], %2, [%3];"
                :: "r"(as_addr + qd * AQ_BYTES),
                   "l"(&g_F[(size_t)(i0 + qd * 32) * ROW_HALVES]),
                   "r"((uint32_t)AQ_BYTES), "r"(mb_base + qd * 8) : "memory");
        }
    }

    // ---- ldmatrix lane roles ----
    int a_r = (lane & 7) + ((lane >> 3) & 1) * 8;
    int a_ck = (lane >> 4) & 1;
    int b_r = (lane & 7) + ((lane >> 4) & 1) * 8;
    int b_ck = (lane >> 3) & 1;

    uint32_t a_rowaddr[2]; int a_rm[2];
#pragma unroll
    for (int mt = 0; mt < 2; mt++) {
        int row = wm * 32 + mt * 16 + a_r;
        a_rowaddr[mt] = as_addr + row * ROW_BYTES;
        a_rm[mt] = row & 7;
    }
    int b_row = wn * 16 + b_r;
    uint32_t b_rowaddr = bs_addr + b_row * ROW_BYTES;
    int b_rm = b_row & 7;

    float acc[2][2][4];
#pragma unroll
    for (int mt = 0; mt < 2; mt++)
#pragma unroll
        for (int nt = 0; nt < 2; nt++)
#pragma unroll
            for (int r = 0; r < 4; r++) acc[mt][nt][r] = 0.f;

    // wait: B + own A quarter only
    mbar_wait(mb_base + 4 * 8);
    mbar_wait(mb_base + wm * 8);

    // ---- mainloop: 16 k16 steps ----
#pragma unroll
    for (int k16 = 0; k16 < 16; k16++) {
        uint32_t afr[2][4], bfr[2][2];
#pragma unroll
        for (int mt = 0; mt < 2; mt++) {
            uint32_t addr = a_rowaddr[mt] +
                (uint32_t)((((2 * k16 + a_ck) ^ a_rm[mt]) << 4));
            asm("ldmatrix.sync.aligned.m8n8.x4.shared.b16 {%0,%1,%2,%3}, [%4];"
                : "=r"(afr[mt][0]), "=r"(afr[mt][1]),
                  "=r"(afr[mt][2]), "=r"(afr[mt][3])
                : "r"(addr) : "memory");
        }
        {
            uint32_t addr = b_rowaddr +
                (uint32_t)((((2 * k16 + b_ck) ^ b_rm) << 4));
            asm("ldmatrix.sync.aligned.m8n8.x4.shared.b16 {%0,%1,%2,%3}, [%4];"
                : "=r"(bfr[0][0]), "=r"(bfr[0][1]),
                  "=r"(bfr[1][0]), "=r"(bfr[1][1])
                : "r"(addr) : "memory");
        }
#pragma unroll
        for (int mt = 0; mt < 2; mt++)
#pragma unroll
            for (int nt = 0; nt < 2; nt++) {
                asm("mma.sync.aligned.m16n8k16.row.col.f32.f16.f16.f32 "
                    "{%0,%1,%2,%3}, {%4,%5,%6,%7}, {%8,%9}, {%0,%1,%2,%3};"
                    : "+f"(acc[mt][nt][0]), "+f"(acc[mt][nt][1]),
                      "+f"(acc[mt][nt][2]), "+f"(acc[mt][nt][3])
                    : "r"(afr[mt][0]), "r"(afr[mt][1]),
                      "r"(afr[mt][2]), "r"(afr[mt][3]),
                      "r"(bfr[nt][0]), "r"(bfr[nt][1]));
            }
    }

    // ---- epilogue ----
#pragma unroll
    for (int mt = 0; mt < 2; mt++) {
        int rowg = i0 + wm * 32 + mt * 16 + grp;
#pragma unroll
        for (int nt = 0; nt < 2; nt++) {
            int colg = j0 + wn * 16 + nt * 8 + 2 * tig;
            float2 o0 = make_float2(fabsf(acc[mt][nt][0]), fabsf(acc[mt][nt][1]));
            float2 o1 = make_float2(fabsf(acc[mt][nt][2]), fabsf(acc[mt][nt][3]));
            *(float2*)&C[(size_t)rowg * NROWS + colg] = o0;
            *(float2*)&C[(size_t)(rowg + 8) * NROWS + colg] = o1;
        }
    }
}

// ---------------------------------------------------------------------------
extern "C" void kernel_launch(void* const* d_in, const int* in_sizes, int n_in,
                              void* d_out, int out_size) {
    const float* a = (const float*)d_in[0];       // [1024,4]
    const float* b = (const float*)d_in[1];       // [1024,4]
    const float* params = (const float*)d_in[2];  // [2,4,3]
    float* out = (float*)d_out;                   // [1024,1024]

    cudaFuncSetAttribute(gemm_f16_abs,
                         cudaFuncAttributeMaxDynamicSharedMemorySize, GEMM_SMEM);

    build_features<<<F_BLOCKS + G_BLOCKS, 128>>>(a, b, params);

    dim3 grid(NROWS / BN, NROWS / BM);   // (16, 8) = 128 blocks, single wave
    gemm_f16_abs<<<grid, 512, GEMM_SMEM>>>(out);
}